// round 10
// baseline (speedup 1.0000x reference)
#include <cuda_runtime.h>
#include <math.h>

// ---------------------------------------------------------------------------
// SCRFD post-processing: decode -> symmetric rank-count (exact stable argsort)
//                        -> edge list -> smem Jacobi NMS -> masked outputs
//
// Output layout (float32, 134400 elems):
//   [0      : 33600 )  boxes  (sorted, masked)  [8400,4]
//   [33600  : 42000 )  scores (sorted, masked)  [8400]
//   [42000  : 126000)  kps    (sorted, masked)  [8400,10]
//   [126000 : 134400)  keep   (0.0 / 1.0)       [8400]
// ---------------------------------------------------------------------------

#define NTOT 8400
#define TILE 64
#define NT   132                 // 8448 / 64
#define NPADR (NT * TILE)        // 8448
#define SCORE_T 0.5f
#define NMS_T   0.4f
#define EDGE_CAP (1 << 22)       // 4.2M edges (test data: a few hundred)
#define ESMEM 16384              // edges cached in smem when ne <= this

typedef unsigned long long u64;
typedef unsigned int u32;
typedef unsigned char uc;

__device__ float4 g_box[NTOT];          // decoded boxes (orig order)
__device__ float  g_kps[NTOT * 10];     // decoded keypoints (orig order)
__device__ u64    g_pack[NPADR];        // (orderedKey<<32)|~idx  (strict total order)
__device__ int    g_rank[NPADR];        // # elements that sort before me
__device__ float  g_skey[NTOT];         // sorted scores
__device__ int    g_sidx[NTOT];         // sorted -> orig index
__device__ float4 g_sbox[NTOT];         // sorted boxes
__device__ float  g_area[NTOT];         // sorted areas
__device__ int    g_nedges;
__device__ u32    g_edges[EDGE_CAP];    // (i<<16)|j, j<i, IoU>NMS_T, i valid
__device__ uc     g_keep[NTOT];

// ---------------------------------------------------------------------------
__global__ void decode_kernel(const float* __restrict__ s0, const float* __restrict__ b0, const float* __restrict__ k0,
                              const float* __restrict__ s1, const float* __restrict__ b1, const float* __restrict__ k1,
                              const float* __restrict__ s2, const float* __restrict__ b2, const float* __restrict__ k2)
{
    int n = blockIdx.x * blockDim.x + threadIdx.x;
    if (n >= NPADR) return;
    if (n == 0) g_nedges = 0;           // fresh each replay (runs before edge_kernel)
    g_rank[n] = 0;
    if (n >= NTOT) {                    // padding: sorts after everything real
        g_pack[n] = (u64)(u32)(~n);     // hi=0 < any real key (real hi has top bit set)
        return;
    }

    const float *sp, *bp, *kp;
    int local, fw;
    float st;
    if (n < 6400)      { sp = s0; bp = b0; kp = k0; local = n;        fw = 80; st = 8.0f;  }
    else if (n < 8000) { sp = s1; bp = b1; kp = k1; local = n - 6400; fw = 40; st = 16.0f; }
    else               { sp = s2; bp = b2; kp = k2; local = n - 8000; fw = 20; st = 32.0f; }

    float px = (float)(local % fw) * st;   // exact (int * pow2)
    float py = (float)(local / fw) * st;

    // sigmoid in double: essentially correctly rounded -> monotone ordering
    // (ordering verified vs JAX in R7/R8).
    float x = sp[local];
    float s = (float)(1.0 / (1.0 + exp(-(double)x)));

    // strides are powers of two -> b*st exact -> decode bit-exact vs IEEE ref
    float4 d = ((const float4*)bp)[local];
    float4 bb;
    bb.x = px - d.x * st;
    bb.y = py - d.y * st;
    bb.z = px + d.z * st;
    bb.w = py + d.w * st;
    g_box[n] = bb;

#pragma unroll
    for (int q = 0; q < 10; q++) {
        float base = (q & 1) ? py : px;
        g_kps[n * 10 + q] = base + kp[local * 10 + q] * st;
    }

    // strict total order key: (score desc, idx asc). sigmoid>0 -> sign clear,
    // XOR 0x80000000 makes uint order match float order (top bit set).
    u32 okey = __float_as_uint(s) ^ 0x80000000u;
    g_pack[n] = ((u64)okey << 32) | (u32)(~n);
}

// ---------------------------------------------------------------------------
// Symmetric rank-by-counting: every unordered pair compared exactly once.
// For pair (i,j): if pack[j] > pack[i], j sorts before i -> rank[i]++,
// else rank[j]++. Loser-side counts come from popc(~ballot) — no 2nd compare.
// Tile (a,b) blocks with a<=b; warp w handles i-half (w&1) x j-half (w>>1).
__global__ void rank_pairs_kernel()
{
    int a = blockIdx.x, b = blockIdx.y;
    if (a > b) return;

    __shared__ u64 ka[TILE], kb[TILE];
    __shared__ int cb[TILE];

    int t = threadIdx.x;                 // 128 threads
    if (t < TILE) { ka[t] = g_pack[a * TILE + t]; cb[t] = 0; }
    else          { kb[t - TILE] = g_pack[b * TILE + (t - TILE)]; }
    __syncthreads();

    int lane = t & 31;
    int warp = t >> 5;
    int ih = warp & 1, jh = warp >> 1;
    int il = ih * 32 + lane;
    u64 ki = ka[il];
    int cntI = 0;

    if (a == b) {
        int gi = a * TILE + il;
#pragma unroll 4
        for (int jj = 0; jj < 32; jj++) {
            int jl = jh * 32 + jj;
            int gj = b * TILE + jl;
            bool vp = (gj > gi);                      // each pair once
            bool jb = (kb[jl] > ki);                  // j beats i
            cntI += (vp && jb) ? 1 : 0;
            unsigned m = __ballot_sync(0xffffffffu, vp && !jb);
            if (lane == 0 && m) atomicAdd(&cb[jl], __popc(m));
        }
    } else {
#pragma unroll 4
        for (int jj = 0; jj < 32; jj++) {
            int jl = jh * 32 + jj;
            bool jb = (kb[jl] > ki);
            cntI += jb ? 1 : 0;
            unsigned m = __ballot_sync(0xffffffffu, !jb);
            if (lane == 0 && m) atomicAdd(&cb[jl], __popc(m));
        }
    }

    if (cntI) atomicAdd(&g_rank[a * TILE + il], cntI);
    __syncthreads();
    if (t < TILE && cb[t]) atomicAdd(&g_rank[b * TILE + t], cb[t]);
}

// ---------------------------------------------------------------------------
__global__ void scatter_kernel()
{
    int n = blockIdx.x * blockDim.x + threadIdx.x;
    if (n >= NTOT) return;
    int r = g_rank[n];                   // exact permutation of 0..NTOT-1
    u32 okey = (u32)(g_pack[n] >> 32);
    g_skey[r] = __uint_as_float(okey ^ 0x80000000u);
    g_sidx[r] = n;
    float4 bx = g_box[n];
    g_sbox[r] = bx;
    g_area[r] = __fmul_rn(__fsub_rn(bx.z, bx.x), __fsub_rn(bx.w, bx.y));
}

// ---------------------------------------------------------------------------
// Emit suppression edges (i,j): j<i, IoU>NMS_T, for valid i only (validity is
// a prefix of the descending sort, so all j<i are then valid too).
// IoU arithmetic replicates JAX bit-for-bit (rn intrinsics block contraction).
__global__ void edge_kernel()
{
    int i = blockIdx.x;
    if (i == 0) return;
    if (g_skey[i] <= SCORE_T) return;    // invalid prefix pruned
    float4 bi = g_sbox[i];
    float  ai = g_area[i];
    for (int j = threadIdx.x; j < i; j += blockDim.x) {
        float4 bj = g_sbox[j];
        float ltx = fmaxf(bi.x, bj.x);
        float lty = fmaxf(bi.y, bj.y);
        float rbx = fminf(bi.z, bj.z);
        float rby = fminf(bi.w, bj.w);
        float w = fmaxf(__fsub_rn(rbx, ltx), 0.0f);
        float h = fmaxf(__fsub_rn(rby, lty), 0.0f);
        float inter = __fmul_rn(w, h);
        if (inter > 0.0f) {
            float denom = __fadd_rn(__fsub_rn(__fadd_rn(ai, g_area[j]), inter), 1e-9f);
            float iou = __fdiv_rn(inter, denom);
            if (iou > NMS_T) {
                int pos = atomicAdd(&g_nedges, 1);
                if (pos < EDGE_CAP) g_edges[pos] = ((u32)i << 16) | (u32)j;
            }
        }
    }
}

// ---------------------------------------------------------------------------
// Greedy NMS = unique fixpoint of keep[i] = valid[i] && !any((i,j): keep[j])
// on the j<i DAG. Edge-centric Jacobi in shared memory; converges within
// (chain depth + 1) rounds, "no change" detection is exact, NTOT+1 cap is a
// hard guarantee. Non-target items stay keep=valid (no predecessors).
__global__ void nms_kernel()
{
    extern __shared__ char sm[];
    u32* es   = (u32*)sm;                     // [ESMEM]
    uc* valid = (uc*)(es + ESMEM);            // [NTOT]
    uc* keep  = valid + NTOT;                 // [NTOT]
    uc* sup   = keep + NTOT;                  // [NTOT]
    __shared__ int changed;

    int tid = threadIdx.x;
    int ne = g_nedges;
    if (ne > EDGE_CAP) ne = EDGE_CAP;
    bool use_s = (ne <= ESMEM);

    if (use_s)
        for (int e = tid; e < ne; e += blockDim.x) es[e] = g_edges[e];
    for (int p = tid; p < NTOT; p += blockDim.x) {
        uc v = (g_skey[p] > SCORE_T) ? 1 : 0;
        valid[p] = v;
        keep[p] = v;
    }
    __syncthreads();
    const u32* E = use_s ? es : g_edges;

    for (int it = 0; it < NTOT + 1; it++) {
        if (tid == 0) changed = 0;
        for (int e = tid; e < ne; e += blockDim.x)       // clear target sups
            sup[E[e] >> 16] = 0;
        __syncthreads();
        for (int e = tid; e < ne; e += blockDim.x) {     // mark suppressed
            u32 x = E[e];
            if (keep[x & 0xffffu]) sup[x >> 16] = 1;
        }
        __syncthreads();
        for (int e = tid; e < ne; e += blockDim.x) {     // update targets
            int i = (int)(E[e] >> 16);
            uc nv = (valid[i] && !sup[i]) ? 1 : 0;
            if (keep[i] != nv) { keep[i] = nv; changed = 1; }
        }
        __syncthreads();
        int ch = changed;
        __syncthreads();
        if (!ch) break;
    }

    for (int p = tid; p < NTOT; p += blockDim.x) g_keep[p] = keep[p];
}

// ---------------------------------------------------------------------------
__global__ void output_kernel(float* __restrict__ out)
{
    int p = blockIdx.x * blockDim.x + threadIdx.x;
    if (p >= NTOT) return;
    float m = g_keep[p] ? 1.0f : 0.0f;
    float4 b = g_sbox[p];
    out[p * 4 + 0] = b.x * m;
    out[p * 4 + 1] = b.y * m;
    out[p * 4 + 2] = b.z * m;
    out[p * 4 + 3] = b.w * m;
    out[33600 + p] = g_skey[p] * m;
    int j = g_sidx[p];
#pragma unroll
    for (int q = 0; q < 10; q++)
        out[42000 + p * 10 + q] = g_kps[j * 10 + q] * m;
    out[126000 + p] = m;
}

// ---------------------------------------------------------------------------
extern "C" void kernel_launch(void* const* d_in, const int* in_sizes, int n_in,
                              void* d_out, int out_size)
{
    const float *s0, *b0, *k0, *s1, *b1, *k1, *s2, *b2, *k2;
    // dict-insertion order (score0,bbox0,kps0,...) vs signature order
    if (n_in >= 9 && in_sizes[1] == 25600) {
        s0 = (const float*)d_in[0]; b0 = (const float*)d_in[1]; k0 = (const float*)d_in[2];
        s1 = (const float*)d_in[3]; b1 = (const float*)d_in[4]; k1 = (const float*)d_in[5];
        s2 = (const float*)d_in[6]; b2 = (const float*)d_in[7]; k2 = (const float*)d_in[8];
    } else {
        s0 = (const float*)d_in[0]; s1 = (const float*)d_in[1]; s2 = (const float*)d_in[2];
        b0 = (const float*)d_in[3]; b1 = (const float*)d_in[4]; b2 = (const float*)d_in[5];
        k0 = (const float*)d_in[6]; k1 = (const float*)d_in[7]; k2 = (const float*)d_in[8];
    }

    const int nms_smem = ESMEM * 4 + 3 * NTOT;   // 90,736 B
    cudaFuncSetAttribute(nms_kernel, cudaFuncAttributeMaxDynamicSharedMemorySize,
                         nms_smem);              // immediate host API, idempotent

    decode_kernel<<<(NPADR + 255) / 256, 256>>>(s0, b0, k0, s1, b1, k1, s2, b2, k2);
    rank_pairs_kernel<<<dim3(NT, NT), 128>>>();
    scatter_kernel<<<(NTOT + 255) / 256, 256>>>();
    edge_kernel<<<NTOT, 128>>>();
    nms_kernel<<<1, 1024, nms_smem>>>();
    output_kernel<<<(NTOT + 255) / 256, 256>>>((float*)d_out);
}